// round 8
// baseline (speedup 1.0000x reference)
#include <cuda_runtime.h>
#include <cuda_bf16.h>

#define BATCH 512
#define SEQ   2048
#define NT    48          // NUM_TAGS
#define NTP   64          // padded (threads per chain)
#define BIAS  4.5f
#define RESCALE_MASK 7    // rescale every 8 steps

__device__ float g_part[BATCH];
__device__ float g_score[BATCH];

// One block per batch chain. 64 threads; thread j (<48) owns output tag j.
// Linear-domain forward: u[j] = exp(alpha[j] - s). Per step:
//   w[j]  = sum_i u[i] * expT[i][j]          (48-term dot, expT column in regs)
//   u'[j] = w[j] * exp(emit[t][j] - BIAS),   s += BIAS
// Periodic max-rescale keeps u in fp32 range. Path score computed inline.
__global__ void __launch_bounds__(NTP)
crf_forward(const float* __restrict__ em,      // [B,S,48]
            const float* __restrict__ trans,   // [48,48]
            const float* __restrict__ startt,  // [48]
            const float* __restrict__ endt,    // [48]
            const int*   __restrict__ tags,    // [B,S]
            const float* __restrict__ mask)    // [B,S]
{
    const int b    = blockIdx.x;
    const int j    = threadIdx.x;        // 0..63
    const int lane = j & 31;
    const int wrp  = j >> 5;

    __shared__ __align__(16) float ubuf[2][NTP];
    __shared__ float tsh[NT * NT];       // raw transitions (for path score)
    __shared__ float red[4];

    // expT column j into registers (0 for padded lanes -> padded u stays 0)
    float Mreg[NT];
    const bool act = (j < NT);
    #pragma unroll
    for (int i = 0; i < NT; i++) {
        float tv = act ? trans[i * NT + j] : 0.0f;
        Mreg[i]  = act ? __expf(tv) : 0.0f;
    }
    for (int k = j; k < NT * NT; k += NTP) tsh[k] = trans[k];

    const float* emb = em   + (size_t)b * SEQ * NT;
    const int*   tgb = tags + (size_t)b * SEQ;
    const float* mkb = mask + (size_t)b * SEQ;

    // ---- t = 0 init ----
    float e0 = act ? emb[j] : 0.0f;
    float u  = act ? __expf(startt[j] + e0) : 0.0f;
    float s  = 0.0f;                      // identical scalar on every thread

    const int tag0 = tgb[0];
    float scorep = (j == tag0) ? (startt[j] + e0) : 0.0f;
    int   prev   = tag0;
    float msum   = mkb[0];                // tracked identically by all threads

    float* ucur = ubuf[0];
    float* unxt = ubuf[1];
    ucur[j] = u;
    __syncthreads();

    const float EXP_NEG_BIAS = __expf(-BIAS);

    #pragma unroll 1
    for (int t = 1; t < SEQ; t++) {
        // ---- dot: w = u . expT[:,j]  (broadcast LDS.128 reads, 4 accums) ----
        float a0 = 0.f, a1 = 0.f, a2 = 0.f, a3 = 0.f;
        const float4* uv = (const float4*)ucur;
        #pragma unroll
        for (int q = 0; q < NT / 4; q++) {
            float4 vv = uv[q];
            a0 = fmaf(vv.x, Mreg[4 * q + 0], a0);
            a1 = fmaf(vv.y, Mreg[4 * q + 1], a1);
            a2 = fmaf(vv.z, Mreg[4 * q + 2], a2);
            a3 = fmaf(vv.w, Mreg[4 * q + 3], a3);
        }
        float w = (a0 + a1) + (a2 + a3);

        float ev   = act ? emb[(size_t)t * NT + j] : 0.0f;
        float m    = mkb[t];
        int   tagt = tgb[t];

        float unew = w * __expf(ev - BIAS);
        u = (m != 0.0f) ? unew : (u * EXP_NEG_BIAS);
        s += BIAS;

        // ---- inline path score ----
        if (j == tagt) scorep += (tsh[prev * NT + j] + ev) * m;
        prev  = tagt;
        msum += m;

        // ---- periodic rescale (uniform branch) ----
        if ((t & RESCALE_MASK) == RESCALE_MASK) {
            float x = u;
            #pragma unroll
            for (int o = 16; o > 0; o >>= 1)
                x = fmaxf(x, __shfl_xor_sync(0xffffffffu, x, o));
            if (lane == 0) red[wrp] = x;
            __syncthreads();
            float mx = fmaxf(red[0], red[1]);
            if (mx > 0.0f) {
                u *= (1.0f / mx);
                s += __logf(mx);
            }
        }

        unxt[j] = u;
        __syncthreads();
        float* tmp = ucur; ucur = unxt; unxt = tmp;
    }

    // ---- epilogue: partition = log(sum u*exp(end)) + s ; reduce score ----
    float y  = act ? (u * __expf(endt[j])) : 0.0f;
    float sc = scorep;
    #pragma unroll
    for (int o = 16; o > 0; o >>= 1) {
        y  += __shfl_xor_sync(0xffffffffu, y,  o);
        sc += __shfl_xor_sync(0xffffffffu, sc, o);
    }
    if (lane == 0) { red[wrp] = y; red[2 + wrp] = sc; }
    __syncthreads();
    if (j == 0) {
        float tot = red[0] + red[1];
        g_part[b] = __logf(tot) + s;

        int   last_idx = (int)(msum + 0.5f) - 1;
        last_idx = max(0, min(SEQ - 1, last_idx));
        int   ltag = tgb[last_idx];
        g_score[b] = (red[2] + red[3]) + endt[ltag];
    }
}

// out[0] = mean(partition - score) = -mean(score - partition)
__global__ void crf_finalize(float* __restrict__ out)
{
    const int i = threadIdx.x;            // 512 threads
    float v = g_part[i] - g_score[i];
    __shared__ float sh[16];
    #pragma unroll
    for (int o = 16; o > 0; o >>= 1)
        v += __shfl_xor_sync(0xffffffffu, v, o);
    if ((i & 31) == 0) sh[i >> 5] = v;
    __syncthreads();
    if (i < 16) {
        float x = sh[i];
        #pragma unroll
        for (int o = 8; o > 0; o >>= 1)
            x += __shfl_xor_sync(0x0000ffffu, x, o);
        if (i == 0) out[0] = x * (1.0f / (float)BATCH);
    }
}

extern "C" void kernel_launch(void* const* d_in, const int* in_sizes, int n_in,
                              void* d_out, int out_size)
{
    const float* em     = (const float*)d_in[0];  // emissions [512,2048,48]
    const float* trans  = (const float*)d_in[1];  // transitions [48,48]
    const float* startt = (const float*)d_in[2];  // start_transitions [48]
    const float* endt   = (const float*)d_in[3];  // end_transitions [48]
    const int*   tags   = (const int*)  d_in[4];  // tags [512,2048]
    const float* mask   = (const float*)d_in[5];  // mask [512,2048]
    float* out = (float*)d_out;

    crf_forward<<<BATCH, NTP>>>(em, trans, startt, endt, tags, mask);
    crf_finalize<<<1, BATCH>>>(out);
}

// round 9
// speedup vs baseline: 1.0225x; 1.0225x over previous
#include <cuda_runtime.h>
#include <cuda_bf16.h>

#define BATCH 512
#define SEQ   2048
#define NT    48          // NUM_TAGS
#define NTP   64          // padded (threads per chain)
#define BIAS  4.5f
#define RESCALE_MASK 7    // rescale every 8 steps

__device__ float g_part[BATCH];
__device__ float g_score[BATCH];

// One block per batch chain. 64 threads; thread j (<48) owns output tag j.
// Linear-domain forward: u[j] = exp(alpha[j] - s). Per step:
//   w[j]  = sum_i u[i] * expT[i][j]          (48-term dot, expT column in regs)
//   u'[j] = w[j] * exp(emit[t][j] - BIAS),   s += BIAS
// Periodic max-rescale keeps u in fp32 range. Path score computed inline.
__global__ void __launch_bounds__(NTP)
crf_forward(const float* __restrict__ em,      // [B,S,48]
            const float* __restrict__ trans,   // [48,48]
            const float* __restrict__ startt,  // [48]
            const float* __restrict__ endt,    // [48]
            const int*   __restrict__ tags,    // [B,S]
            const float* __restrict__ mask)    // [B,S]
{
    const int b    = blockIdx.x;
    const int j    = threadIdx.x;        // 0..63
    const int lane = j & 31;
    const int wrp  = j >> 5;

    __shared__ __align__(16) float ubuf[2][NTP];
    __shared__ float tsh[NT * NT];       // raw transitions (for path score)
    __shared__ float red[4];

    // expT column j into registers (0 for padded lanes -> padded u stays 0)
    float Mreg[NT];
    const bool act = (j < NT);
    #pragma unroll
    for (int i = 0; i < NT; i++) {
        float tv = act ? trans[i * NT + j] : 0.0f;
        Mreg[i]  = act ? __expf(tv) : 0.0f;
    }
    for (int k = j; k < NT * NT; k += NTP) tsh[k] = trans[k];

    const float* emb = em   + (size_t)b * SEQ * NT;
    const int*   tgb = tags + (size_t)b * SEQ;
    const float* mkb = mask + (size_t)b * SEQ;

    // ---- t = 0 init ----
    float e0 = act ? emb[j] : 0.0f;
    float u  = act ? __expf(startt[j] + e0) : 0.0f;
    float s  = 0.0f;                      // identical scalar on every thread

    const int tag0 = tgb[0];
    float scorep = (j == tag0) ? (startt[j] + e0) : 0.0f;
    int   prev   = tag0;
    float msum   = mkb[0];                // tracked identically by all threads

    float* ucur = ubuf[0];
    float* unxt = ubuf[1];
    ucur[j] = u;
    __syncthreads();

    const float EXP_NEG_BIAS = __expf(-BIAS);

    #pragma unroll 1
    for (int t = 1; t < SEQ; t++) {
        // ---- dot: w = u . expT[:,j]  (broadcast LDS.128 reads, 4 accums) ----
        float a0 = 0.f, a1 = 0.f, a2 = 0.f, a3 = 0.f;
        const float4* uv = (const float4*)ucur;
        #pragma unroll
        for (int q = 0; q < NT / 4; q++) {
            float4 vv = uv[q];
            a0 = fmaf(vv.x, Mreg[4 * q + 0], a0);
            a1 = fmaf(vv.y, Mreg[4 * q + 1], a1);
            a2 = fmaf(vv.z, Mreg[4 * q + 2], a2);
            a3 = fmaf(vv.w, Mreg[4 * q + 3], a3);
        }
        float w = (a0 + a1) + (a2 + a3);

        float ev   = act ? emb[(size_t)t * NT + j] : 0.0f;
        float m    = mkb[t];
        int   tagt = tgb[t];

        float unew = w * __expf(ev - BIAS);
        u = (m != 0.0f) ? unew : (u * EXP_NEG_BIAS);
        s += BIAS;

        // ---- inline path score ----
        if (j == tagt) scorep += (tsh[prev * NT + j] + ev) * m;
        prev  = tagt;
        msum += m;

        // ---- periodic rescale (uniform branch) ----
        if ((t & RESCALE_MASK) == RESCALE_MASK) {
            float x = u;
            #pragma unroll
            for (int o = 16; o > 0; o >>= 1)
                x = fmaxf(x, __shfl_xor_sync(0xffffffffu, x, o));
            if (lane == 0) red[wrp] = x;
            __syncthreads();
            float mx = fmaxf(red[0], red[1]);
            if (mx > 0.0f) {
                u *= (1.0f / mx);
                s += __logf(mx);
            }
        }

        unxt[j] = u;
        __syncthreads();
        float* tmp = ucur; ucur = unxt; unxt = tmp;
    }

    // ---- epilogue: partition = log(sum u*exp(end)) + s ; reduce score ----
    float y  = act ? (u * __expf(endt[j])) : 0.0f;
    float sc = scorep;
    #pragma unroll
    for (int o = 16; o > 0; o >>= 1) {
        y  += __shfl_xor_sync(0xffffffffu, y,  o);
        sc += __shfl_xor_sync(0xffffffffu, sc, o);
    }
    if (lane == 0) { red[wrp] = y; red[2 + wrp] = sc; }
    __syncthreads();
    if (j == 0) {
        float tot = red[0] + red[1];
        g_part[b] = __logf(tot) + s;

        int   last_idx = (int)(msum + 0.5f) - 1;
        last_idx = max(0, min(SEQ - 1, last_idx));
        int   ltag = tgb[last_idx];
        g_score[b] = (red[2] + red[3]) + endt[ltag];
    }
}

// out[0] = mean(partition - score) = -mean(score - partition)
__global__ void crf_finalize(float* __restrict__ out)
{
    const int i = threadIdx.x;            // 512 threads
    float v = g_part[i] - g_score[i];
    __shared__ float sh[16];
    #pragma unroll
    for (int o = 16; o > 0; o >>= 1)
        v += __shfl_xor_sync(0xffffffffu, v, o);
    if ((i & 31) == 0) sh[i >> 5] = v;
    __syncthreads();
    if (i < 16) {
        float x = sh[i];
        #pragma unroll
        for (int o = 8; o > 0; o >>= 1)
            x += __shfl_xor_sync(0x0000ffffu, x, o);
        if (i == 0) out[0] = x * (1.0f / (float)BATCH);
    }
}

extern "C" void kernel_launch(void* const* d_in, const int* in_sizes, int n_in,
                              void* d_out, int out_size)
{
    const float* em     = (const float*)d_in[0];  // emissions [512,2048,48]
    const float* trans  = (const float*)d_in[1];  // transitions [48,48]
    const float* startt = (const float*)d_in[2];  // start_transitions [48]
    const float* endt   = (const float*)d_in[3];  // end_transitions [48]
    const int*   tags   = (const int*)  d_in[4];  // tags [512,2048]
    const float* mask   = (const float*)d_in[5];  // mask [512,2048]
    float* out = (float*)d_out;

    crf_forward<<<BATCH, NTP>>>(em, trans, startt, endt, tags, mask);
    crf_finalize<<<1, BATCH>>>(out);
}

// round 10
// speedup vs baseline: 1.0247x; 1.0022x over previous
#include <cuda_runtime.h>
#include <cuda_bf16.h>

#define BATCH 512
#define SEQ   2048
#define NT    48          // NUM_TAGS
#define NTP   64          // padded (threads per chain)
#define BIAS  4.5f
#define RESCALE_MASK 7    // rescale every 8 steps

__device__ float g_part[BATCH];
__device__ float g_score[BATCH];

// One block per batch chain. 64 threads; thread j (<48) owns output tag j.
// Linear-domain forward: u[j] = exp(alpha[j] - s). Per step:
//   w[j]  = sum_i u[i] * expT[i][j]          (48-term dot, expT column in regs)
//   u'[j] = w[j] * exp(emit[t][j] - BIAS),   s += BIAS
// Periodic max-rescale keeps u in fp32 range. Path score computed inline.
__global__ void __launch_bounds__(NTP)
crf_forward(const float* __restrict__ em,      // [B,S,48]
            const float* __restrict__ trans,   // [48,48]
            const float* __restrict__ startt,  // [48]
            const float* __restrict__ endt,    // [48]
            const int*   __restrict__ tags,    // [B,S]
            const float* __restrict__ mask)    // [B,S]
{
    const int b    = blockIdx.x;
    const int j    = threadIdx.x;        // 0..63
    const int lane = j & 31;
    const int wrp  = j >> 5;

    __shared__ __align__(16) float ubuf[2][NTP];
    __shared__ float tsh[NT * NT];       // raw transitions (for path score)
    __shared__ float red[4];

    // expT column j into registers (0 for padded lanes -> padded u stays 0)
    float Mreg[NT];
    const bool act = (j < NT);
    #pragma unroll
    for (int i = 0; i < NT; i++) {
        float tv = act ? trans[i * NT + j] : 0.0f;
        Mreg[i]  = act ? __expf(tv) : 0.0f;
    }
    for (int k = j; k < NT * NT; k += NTP) tsh[k] = trans[k];

    const float* emb = em   + (size_t)b * SEQ * NT;
    const int*   tgb = tags + (size_t)b * SEQ;
    const float* mkb = mask + (size_t)b * SEQ;

    // ---- t = 0 init ----
    float e0 = act ? emb[j] : 0.0f;
    float u  = act ? __expf(startt[j] + e0) : 0.0f;
    float s  = 0.0f;                      // identical scalar on every thread

    const int tag0 = tgb[0];
    float scorep = (j == tag0) ? (startt[j] + e0) : 0.0f;
    int   prev   = tag0;
    float msum   = mkb[0];                // tracked identically by all threads

    float* ucur = ubuf[0];
    float* unxt = ubuf[1];
    ucur[j] = u;
    __syncthreads();

    const float EXP_NEG_BIAS = __expf(-BIAS);

    #pragma unroll 1
    for (int t = 1; t < SEQ; t++) {
        // ---- dot: w = u . expT[:,j]  (broadcast LDS.128 reads, 4 accums) ----
        float a0 = 0.f, a1 = 0.f, a2 = 0.f, a3 = 0.f;
        const float4* uv = (const float4*)ucur;
        #pragma unroll
        for (int q = 0; q < NT / 4; q++) {
            float4 vv = uv[q];
            a0 = fmaf(vv.x, Mreg[4 * q + 0], a0);
            a1 = fmaf(vv.y, Mreg[4 * q + 1], a1);
            a2 = fmaf(vv.z, Mreg[4 * q + 2], a2);
            a3 = fmaf(vv.w, Mreg[4 * q + 3], a3);
        }
        float w = (a0 + a1) + (a2 + a3);

        float ev   = act ? emb[(size_t)t * NT + j] : 0.0f;
        float m    = mkb[t];
        int   tagt = tgb[t];

        float unew = w * __expf(ev - BIAS);
        u = (m != 0.0f) ? unew : (u * EXP_NEG_BIAS);
        s += BIAS;

        // ---- inline path score ----
        if (j == tagt) scorep += (tsh[prev * NT + j] + ev) * m;
        prev  = tagt;
        msum += m;

        // ---- periodic rescale (uniform branch) ----
        if ((t & RESCALE_MASK) == RESCALE_MASK) {
            float x = u;
            #pragma unroll
            for (int o = 16; o > 0; o >>= 1)
                x = fmaxf(x, __shfl_xor_sync(0xffffffffu, x, o));
            if (lane == 0) red[wrp] = x;
            __syncthreads();
            float mx = fmaxf(red[0], red[1]);
            if (mx > 0.0f) {
                u *= (1.0f / mx);
                s += __logf(mx);
            }
        }

        unxt[j] = u;
        __syncthreads();
        float* tmp = ucur; ucur = unxt; unxt = tmp;
    }

    // ---- epilogue: partition = log(sum u*exp(end)) + s ; reduce score ----
    float y  = act ? (u * __expf(endt[j])) : 0.0f;
    float sc = scorep;
    #pragma unroll
    for (int o = 16; o > 0; o >>= 1) {
        y  += __shfl_xor_sync(0xffffffffu, y,  o);
        sc += __shfl_xor_sync(0xffffffffu, sc, o);
    }
    if (lane == 0) { red[wrp] = y; red[2 + wrp] = sc; }
    __syncthreads();
    if (j == 0) {
        float tot = red[0] + red[1];
        g_part[b] = __logf(tot) + s;

        int   last_idx = (int)(msum + 0.5f) - 1;
        last_idx = max(0, min(SEQ - 1, last_idx));
        int   ltag = tgb[last_idx];
        g_score[b] = (red[2] + red[3]) + endt[ltag];
    }
}

// out[0] = mean(partition - score) = -mean(score - partition)
__global__ void crf_finalize(float* __restrict__ out)
{
    const int i = threadIdx.x;            // 512 threads
    float v = g_part[i] - g_score[i];
    __shared__ float sh[16];
    #pragma unroll
    for (int o = 16; o > 0; o >>= 1)
        v += __shfl_xor_sync(0xffffffffu, v, o);
    if ((i & 31) == 0) sh[i >> 5] = v;
    __syncthreads();
    if (i < 16) {
        float x = sh[i];
        #pragma unroll
        for (int o = 8; o > 0; o >>= 1)
            x += __shfl_xor_sync(0x0000ffffu, x, o);
        if (i == 0) out[0] = x * (1.0f / (float)BATCH);
    }
}

extern "C" void kernel_launch(void* const* d_in, const int* in_sizes, int n_in,
                              void* d_out, int out_size)
{
    const float* em     = (const float*)d_in[0];  // emissions [512,2048,48]
    const float* trans  = (const float*)d_in[1];  // transitions [48,48]
    const float* startt = (const float*)d_in[2];  // start_transitions [48]
    const float* endt   = (const float*)d_in[3];  // end_transitions [48]
    const int*   tags   = (const int*)  d_in[4];  // tags [512,2048]
    const float* mask   = (const float*)d_in[5];  // mask [512,2048]
    float* out = (float*)d_out;

    crf_forward<<<BATCH, NTP>>>(em, trans, startt, endt, tags, mask);
    crf_finalize<<<1, BATCH>>>(out);
}

// round 11
// speedup vs baseline: 3.0770x; 3.0028x over previous
#include <cuda_runtime.h>
#include <cuda_bf16.h>
#include <cstdint>

#define BATCH 512
#define SEQ   2048
#define NT    48          // NUM_TAGS
#define NTP   64          // padded (threads per chain)
#define BIAS  4.5f

typedef unsigned long long u64;

__device__ float g_part[BATCH];
__device__ float g_score[BATCH];

__device__ __forceinline__ u64 pack2(float lo, float hi) {
    u64 r; asm("mov.b64 %0, {%1, %2};" : "=l"(r) : "f"(lo), "f"(hi)); return r;
}
__device__ __forceinline__ void unpack2(u64 v, float& lo, float& hi) {
    asm("mov.b64 {%0, %1}, %2;" : "=f"(lo), "=f"(hi) : "l"(v));
}
__device__ __forceinline__ u64 fma2(u64 a, u64 b, u64 c) {
    u64 d;
    asm("fma.rn.f32x2 %0, %1, %2, %3;" : "=l"(d) : "l"(a), "l"(b), "l"(c));
    return d;
}

// One block per chain, 64 threads, thread j (<48) owns output tag j.
// Linear-domain forward with:
//  - expT column packed as 24 x f32x2 in registers
//  - dot via ld.shared.v2.b64 + fma.rn.f32x2 (24 packed FMAs, 4 accumulators)
//  - 8-step register prefetch of emissions/mask/tags (hides DRAM latency)
//  - max-rescale every 16 steps
__global__ void __launch_bounds__(NTP)
crf_forward(const float* __restrict__ em,      // [B,S,48]
            const float* __restrict__ trans,   // [48,48]
            const float* __restrict__ startt,  // [48]
            const float* __restrict__ endt,    // [48]
            const int*   __restrict__ tags,    // [B,S]
            const float* __restrict__ mask)    // [B,S]
{
    const int b    = blockIdx.x;
    const int j    = threadIdx.x;        // 0..63
    const int lane = j & 31;
    const int wrp  = j >> 5;

    __shared__ __align__(16) float ubuf[2][NTP];
    __shared__ float tsh[NT * NT];       // raw transitions (for path score)
    __shared__ float red[4];

    const bool act = (j < NT);

    // expT column j packed into 24 f32x2 registers (zeros for padded lanes)
    u64 M2[NT / 2];
    #pragma unroll
    for (int k = 0; k < NT / 2; k++) {
        float lo = act ? __expf(trans[(2 * k)     * NT + j]) : 0.0f;
        float hi = act ? __expf(trans[(2 * k + 1) * NT + j]) : 0.0f;
        M2[k] = pack2(lo, hi);
    }
    for (int k = j; k < NT * NT; k += NTP) tsh[k] = trans[k];

    const float* emb = em   + (size_t)b * SEQ * NT;
    const int*   tgb = tags + (size_t)b * SEQ;
    const float* mkb = mask + (size_t)b * SEQ;

    // ---- t = 0 init ----
    float e0 = act ? emb[j] : 0.0f;
    float u  = act ? __expf(startt[j] + e0) : 0.0f;
    float s  = 0.0f;

    const int tag0 = tgb[0];
    float scorep = (j == tag0) ? (startt[j] + e0) : 0.0f;
    int   prev   = tag0;
    float msum   = mkb[0];

    float*   up_cur = ubuf[0];
    float*   up_nxt = ubuf[1];
    uint32_t ua = (uint32_t)__cvta_generic_to_shared(ubuf[0]);
    uint32_t ub = (uint32_t)__cvta_generic_to_shared(ubuf[1]);

    up_cur[j] = u;
    __syncthreads();

    const float EXP_NEG_BIAS = __expf(-BIAS);

    // ---- prefetch pipeline: fill for t = 1..8 ----
    float evc[8], mc[8];
    int   tc[8];
    #pragma unroll
    for (int k = 0; k < 8; k++) {
        int tt = 1 + k;
        evc[k] = act ? __ldg(&emb[(size_t)tt * NT + j]) : 0.0f;
        mc[k]  = __ldg(&mkb[tt]);
        tc[k]  = __ldg(&tgb[tt]);
    }

#define CRF_STEP(EV, MM, TG)                                                  \
    do {                                                                      \
        u64 a0 = 0ull, a1 = 0ull, a2 = 0ull, a3 = 0ull;                       \
        _Pragma("unroll")                                                     \
        for (int q = 0; q < 12; q++) {                                        \
            u64 p0, p1;                                                       \
            asm volatile("ld.shared.v2.b64 {%0, %1}, [%2];"                   \
                         : "=l"(p0), "=l"(p1) : "r"(ua + q * 16));            \
            if ((q & 1) == 0) { a0 = fma2(p0, M2[2*q], a0);                   \
                                a1 = fma2(p1, M2[2*q+1], a1); }               \
            else              { a2 = fma2(p0, M2[2*q], a2);                   \
                                a3 = fma2(p1, M2[2*q+1], a3); }               \
        }                                                                     \
        float l0,h0,l1,h1,l2,h2,l3,h3;                                        \
        unpack2(a0,l0,h0); unpack2(a1,l1,h1);                                 \
        unpack2(a2,l2,h2); unpack2(a3,l3,h3);                                 \
        float w = ((l0+h0)+(l1+h1)) + ((l2+h2)+(l3+h3));                      \
        float unew = w * __expf((EV) - BIAS);                                 \
        u = ((MM) != 0.0f) ? unew : (u * EXP_NEG_BIAS);                       \
        s += BIAS;                                                            \
        if (j == (TG)) scorep += (tsh[prev * NT + j] + (EV)) * (MM);          \
        prev  = (TG);                                                         \
        msum += (MM);                                                         \
        up_nxt[j] = u;                                                        \
        __syncthreads();                                                      \
        { float* tp = up_cur; up_cur = up_nxt; up_nxt = tp;                   \
          uint32_t ta = ua; ua = ub; ub = ta; }                               \
    } while (0)

    // ---- main loop: 255 groups of 8 steps (t = 1..2040), prefetch depth 8 ----
    #pragma unroll 1
    for (int g = 0; g < 255; g++) {
        const int tb = 1 + g * 8;

        float evn[8], mn[8];
        int   tn[8];
        #pragma unroll
        for (int k = 0; k < 8; k++) {
            int tt = tb + 8 + k;
            tt = (tt < SEQ) ? tt : (SEQ - 1);
            evn[k] = act ? __ldg(&emb[(size_t)tt * NT + j]) : 0.0f;
            mn[k]  = __ldg(&mkb[tt]);
            tn[k]  = __ldg(&tgb[tt]);
        }

        #pragma unroll
        for (int k = 0; k < 8; k++) CRF_STEP(evc[k], mc[k], tc[k]);

        #pragma unroll
        for (int k = 0; k < 8; k++) { evc[k] = evn[k]; mc[k] = mn[k]; tc[k] = tn[k]; }

        // ---- rescale every 16 steps ----
        if (g & 1) {
            float x = u;
            #pragma unroll
            for (int o = 16; o > 0; o >>= 1)
                x = fmaxf(x, __shfl_xor_sync(0xffffffffu, x, o));
            if (lane == 0) red[wrp] = x;
            __syncthreads();
            float mx = fmaxf(red[0], red[1]);
            if (mx > 0.0f) {
                float inv = 1.0f / mx;
                u *= inv;
                s += __logf(mx);
            }
            up_cur[j] = u;      // refresh current buffer with rescaled values
            __syncthreads();
        }
    }

    // ---- tail: t = 2041..2047 (7 steps, already prefetched) ----
    #pragma unroll
    for (int k = 0; k < 7; k++) CRF_STEP(evc[k], mc[k], tc[k]);

#undef CRF_STEP

    // ---- epilogue ----
    float y  = act ? (u * __expf(endt[j])) : 0.0f;
    float sc = scorep;
    #pragma unroll
    for (int o = 16; o > 0; o >>= 1) {
        y  += __shfl_xor_sync(0xffffffffu, y,  o);
        sc += __shfl_xor_sync(0xffffffffu, sc, o);
    }
    if (lane == 0) { red[wrp] = y; red[2 + wrp] = sc; }
    __syncthreads();
    if (j == 0) {
        float tot = red[0] + red[1];
        g_part[b] = __logf(tot) + s;

        int last_idx = (int)(msum + 0.5f) - 1;
        last_idx = max(0, min(SEQ - 1, last_idx));
        int ltag = tgb[last_idx];
        g_score[b] = (red[2] + red[3]) + endt[ltag];
    }
}

// out[0] = mean(partition - score) = -mean(score - partition)
__global__ void crf_finalize(float* __restrict__ out)
{
    const int i = threadIdx.x;            // 512 threads
    float v = g_part[i] - g_score[i];
    __shared__ float sh[16];
    #pragma unroll
    for (int o = 16; o > 0; o >>= 1)
        v += __shfl_xor_sync(0xffffffffu, v, o);
    if ((i & 31) == 0) sh[i >> 5] = v;
    __syncthreads();
    if (i < 16) {
        float x = sh[i];
        #pragma unroll
        for (int o = 8; o > 0; o >>= 1)
            x += __shfl_xor_sync(0x0000ffffu, x, o);
        if (i == 0) out[0] = x * (1.0f / (float)BATCH);
    }
}

extern "C" void kernel_launch(void* const* d_in, const int* in_sizes, int n_in,
                              void* d_out, int out_size)
{
    const float* em     = (const float*)d_in[0];  // emissions [512,2048,48]
    const float* trans  = (const float*)d_in[1];  // transitions [48,48]
    const float* startt = (const float*)d_in[2];  // start_transitions [48]
    const float* endt   = (const float*)d_in[3];  // end_transitions [48]
    const int*   tags   = (const int*)  d_in[4];  // tags [512,2048]
    const float* mask   = (const float*)d_in[5];  // mask [512,2048]
    float* out = (float*)d_out;

    crf_forward<<<BATCH, NTP>>>(em, trans, startt, endt, tags, mask);
    crf_finalize<<<1, BATCH>>>(out);
}

// round 12
// speedup vs baseline: 3.1940x; 1.0380x over previous
#include <cuda_runtime.h>
#include <cuda_bf16.h>
#include <cstdint>

#define BATCH 512
#define SEQ   2048
#define NT    48          // NUM_TAGS
#define NTP   64          // padded (threads per chain)
#define BIAS  4.5f

typedef unsigned long long u64;

__device__ float g_part[BATCH];
__device__ float g_score[BATCH];

__device__ __forceinline__ u64 pack2(float lo, float hi) {
    u64 r; asm("mov.b64 %0, {%1, %2};" : "=l"(r) : "f"(lo), "f"(hi)); return r;
}
__device__ __forceinline__ void unpack2(u64 v, float& lo, float& hi) {
    asm("mov.b64 {%0, %1}, %2;" : "=f"(lo), "=f"(hi) : "l"(v));
}
__device__ __forceinline__ u64 fma2(u64 a, u64 b, u64 c) {
    u64 d;
    asm("fma.rn.f32x2 %0, %1, %2, %3;" : "=l"(d) : "l"(a), "l"(b), "l"(c));
    return d;
}

// One block per chain, 64 threads, thread j (<48) owns output tag j.
// Linear-domain forward with:
//  - expT column packed as 24 x f32x2 in registers
//  - dot via ld.shared.v2.b64 + fma.rn.f32x2 (24 packed FMAs, 4 accumulators)
//  - 8-step register prefetch of emissions/mask/tags (hides DRAM latency)
//  - max-rescale every 16 steps
__global__ void __launch_bounds__(NTP)
crf_forward(const float* __restrict__ em,      // [B,S,48]
            const float* __restrict__ trans,   // [48,48]
            const float* __restrict__ startt,  // [48]
            const float* __restrict__ endt,    // [48]
            const int*   __restrict__ tags,    // [B,S]
            const float* __restrict__ mask)    // [B,S]
{
    const int b    = blockIdx.x;
    const int j    = threadIdx.x;        // 0..63
    const int lane = j & 31;
    const int wrp  = j >> 5;

    __shared__ __align__(16) float ubuf[2][NTP];
    __shared__ float tsh[NT * NT];       // raw transitions (for path score)
    __shared__ float red[4];

    const bool act = (j < NT);

    // expT column j packed into 24 f32x2 registers (zeros for padded lanes)
    u64 M2[NT / 2];
    #pragma unroll
    for (int k = 0; k < NT / 2; k++) {
        float lo = act ? __expf(trans[(2 * k)     * NT + j]) : 0.0f;
        float hi = act ? __expf(trans[(2 * k + 1) * NT + j]) : 0.0f;
        M2[k] = pack2(lo, hi);
    }
    for (int k = j; k < NT * NT; k += NTP) tsh[k] = trans[k];

    const float* emb = em   + (size_t)b * SEQ * NT;
    const int*   tgb = tags + (size_t)b * SEQ;
    const float* mkb = mask + (size_t)b * SEQ;

    // ---- t = 0 init ----
    float e0 = act ? emb[j] : 0.0f;
    float u  = act ? __expf(startt[j] + e0) : 0.0f;
    float s  = 0.0f;

    const int tag0 = tgb[0];
    float scorep = (j == tag0) ? (startt[j] + e0) : 0.0f;
    int   prev   = tag0;
    float msum   = mkb[0];

    float*   up_cur = ubuf[0];
    float*   up_nxt = ubuf[1];
    uint32_t ua = (uint32_t)__cvta_generic_to_shared(ubuf[0]);
    uint32_t ub = (uint32_t)__cvta_generic_to_shared(ubuf[1]);

    up_cur[j] = u;
    __syncthreads();

    const float EXP_NEG_BIAS = __expf(-BIAS);

    // ---- prefetch pipeline: fill for t = 1..8 ----
    float evc[8], mc[8];
    int   tc[8];
    #pragma unroll
    for (int k = 0; k < 8; k++) {
        int tt = 1 + k;
        evc[k] = act ? __ldg(&emb[(size_t)tt * NT + j]) : 0.0f;
        mc[k]  = __ldg(&mkb[tt]);
        tc[k]  = __ldg(&tgb[tt]);
    }

#define CRF_STEP(EV, MM, TG)                                                  \
    do {                                                                      \
        u64 a0 = 0ull, a1 = 0ull, a2 = 0ull, a3 = 0ull;                       \
        _Pragma("unroll")                                                     \
        for (int q = 0; q < 12; q++) {                                        \
            u64 p0, p1;                                                       \
            asm volatile("ld.shared.v2.b64 {%0, %1}, [%2];"                   \
                         : "=l"(p0), "=l"(p1) : "r"(ua + q * 16));            \
            if ((q & 1) == 0) { a0 = fma2(p0, M2[2*q], a0);                   \
                                a1 = fma2(p1, M2[2*q+1], a1); }               \
            else              { a2 = fma2(p0, M2[2*q], a2);                   \
                                a3 = fma2(p1, M2[2*q+1], a3); }               \
        }                                                                     \
        float l0,h0,l1,h1,l2,h2,l3,h3;                                        \
        unpack2(a0,l0,h0); unpack2(a1,l1,h1);                                 \
        unpack2(a2,l2,h2); unpack2(a3,l3,h3);                                 \
        float w = ((l0+h0)+(l1+h1)) + ((l2+h2)+(l3+h3));                      \
        float unew = w * __expf((EV) - BIAS);                                 \
        u = ((MM) != 0.0f) ? unew : (u * EXP_NEG_BIAS);                       \
        s += BIAS;                                                            \
        if (j == (TG)) scorep += (tsh[prev * NT + j] + (EV)) * (MM);          \
        prev  = (TG);                                                         \
        msum += (MM);                                                         \
        up_nxt[j] = u;                                                        \
        __syncthreads();                                                      \
        { float* tp = up_cur; up_cur = up_nxt; up_nxt = tp;                   \
          uint32_t ta = ua; ua = ub; ub = ta; }                               \
    } while (0)

    // ---- main loop: 255 groups of 8 steps (t = 1..2040), prefetch depth 8 ----
    #pragma unroll 1
    for (int g = 0; g < 255; g++) {
        const int tb = 1 + g * 8;

        float evn[8], mn[8];
        int   tn[8];
        #pragma unroll
        for (int k = 0; k < 8; k++) {
            int tt = tb + 8 + k;
            tt = (tt < SEQ) ? tt : (SEQ - 1);
            evn[k] = act ? __ldg(&emb[(size_t)tt * NT + j]) : 0.0f;
            mn[k]  = __ldg(&mkb[tt]);
            tn[k]  = __ldg(&tgb[tt]);
        }

        #pragma unroll
        for (int k = 0; k < 8; k++) CRF_STEP(evc[k], mc[k], tc[k]);

        #pragma unroll
        for (int k = 0; k < 8; k++) { evc[k] = evn[k]; mc[k] = mn[k]; tc[k] = tn[k]; }

        // ---- rescale every 16 steps ----
        if (g & 1) {
            float x = u;
            #pragma unroll
            for (int o = 16; o > 0; o >>= 1)
                x = fmaxf(x, __shfl_xor_sync(0xffffffffu, x, o));
            if (lane == 0) red[wrp] = x;
            __syncthreads();
            float mx = fmaxf(red[0], red[1]);
            if (mx > 0.0f) {
                float inv = 1.0f / mx;
                u *= inv;
                s += __logf(mx);
            }
            up_cur[j] = u;      // refresh current buffer with rescaled values
            __syncthreads();
        }
    }

    // ---- tail: t = 2041..2047 (7 steps, already prefetched) ----
    #pragma unroll
    for (int k = 0; k < 7; k++) CRF_STEP(evc[k], mc[k], tc[k]);

#undef CRF_STEP

    // ---- epilogue ----
    float y  = act ? (u * __expf(endt[j])) : 0.0f;
    float sc = scorep;
    #pragma unroll
    for (int o = 16; o > 0; o >>= 1) {
        y  += __shfl_xor_sync(0xffffffffu, y,  o);
        sc += __shfl_xor_sync(0xffffffffu, sc, o);
    }
    if (lane == 0) { red[wrp] = y; red[2 + wrp] = sc; }
    __syncthreads();
    if (j == 0) {
        float tot = red[0] + red[1];
        g_part[b] = __logf(tot) + s;

        int last_idx = (int)(msum + 0.5f) - 1;
        last_idx = max(0, min(SEQ - 1, last_idx));
        int ltag = tgb[last_idx];
        g_score[b] = (red[2] + red[3]) + endt[ltag];
    }
}

// out[0] = mean(partition - score) = -mean(score - partition)
__global__ void crf_finalize(float* __restrict__ out)
{
    const int i = threadIdx.x;            // 512 threads
    float v = g_part[i] - g_score[i];
    __shared__ float sh[16];
    #pragma unroll
    for (int o = 16; o > 0; o >>= 1)
        v += __shfl_xor_sync(0xffffffffu, v, o);
    if ((i & 31) == 0) sh[i >> 5] = v;
    __syncthreads();
    if (i < 16) {
        float x = sh[i];
        #pragma unroll
        for (int o = 8; o > 0; o >>= 1)
            x += __shfl_xor_sync(0x0000ffffu, x, o);
        if (i == 0) out[0] = x * (1.0f / (float)BATCH);
    }
}

extern "C" void kernel_launch(void* const* d_in, const int* in_sizes, int n_in,
                              void* d_out, int out_size)
{
    const float* em     = (const float*)d_in[0];  // emissions [512,2048,48]
    const float* trans  = (const float*)d_in[1];  // transitions [48,48]
    const float* startt = (const float*)d_in[2];  // start_transitions [48]
    const float* endt   = (const float*)d_in[3];  // end_transitions [48]
    const int*   tags   = (const int*)  d_in[4];  // tags [512,2048]
    const float* mask   = (const float*)d_in[5];  // mask [512,2048]
    float* out = (float*)d_out;

    crf_forward<<<BATCH, NTP>>>(em, trans, startt, endt, tags, mask);
    crf_finalize<<<1, BATCH>>>(out);
}